// round 8
// baseline (speedup 1.0000x reference)
#include <cuda_runtime.h>

#define BB 4096
#define TT 200
#define DD 128
#define KS 5
#define NTHREADS 256

#define STG_T 64                 // tokens staged in smem for pass 2

#define CB_ROWS 16
#define ECHUNK 64
#define WV_P 132                 // padded floats per Wv row (33 float4s, odd -> conflict-free)
#define CB_SMEM ((ECHUNK * WV_P + 2 * CB_ROWS * DD) * 4)

__device__ float g_w[BB * DD];    // normalized attention-weighted sum
__device__ float g_us[BB * DD];   // g * short_term
__device__ float g_omg[BB];       // 1 - g

__device__ __forceinline__ float warp_sum(float v) {
#pragma unroll
    for (int o = 16; o; o >>= 1) v += __shfl_xor_sync(0xffffffffu, v, o);
    return v;
}

__global__ void __launch_bounds__(NTHREADS, 5)
user_enc_kernel(const float* __restrict__ items_g,
                const int* __restrict__ mask_g,
                const float* __restrict__ age_g,
                const float* __restrict__ pop_g,
                const float* __restrict__ Wq,
                const float* __restrict__ Wk,
                const float* __restrict__ gate_w,
                const float* __restrict__ gate_b,
                const float* __restrict__ dalpha) {
    __shared__ float s_stage[STG_T * DD];   // 32 KB: first 64 tokens
    __shared__ float s_mask[TT];
    __shared__ float s_age[TT];
    __shared__ float s_pop[TT];
    __shared__ float s_dlog[TT];
    __shared__ float s_mean[DD];
    __shared__ float s_q[DD];
    __shared__ float s_r[DD];
    __shared__ float s_part[1024];
    __shared__ float s_wm[8];
    __shared__ float s_wz[8];
    __shared__ float s_scal[4];

    const int tid  = threadIdx.x;
    const int lane = tid & 31;
    const int warp = tid >> 5;
    const int b    = blockIdx.x;
    const float NEG_INF = __int_as_float(0xff800000);
    const float* row = items_g + (size_t)b * TT * DD;
    const float4* row4 = (const float4*)row;
    float4* stg4 = (float4*)s_stage;

    // ---- phase 0: metadata + decay-log (parallel) ----
    const float alpha = log1pf(expf(dalpha[0])) + 1e-6f;
    if (tid < TT) {
        int m = mask_g[(size_t)b * TT + tid];
        float a = age_g[(size_t)b * TT + tid];
        s_mask[tid] = m ? 1.f : 0.f;
        s_age[tid]  = a;
        s_pop[tid]  = pop_g[(size_t)b * TT + tid];
        s_dlog[tid] = m ? __logf(__expf(-alpha * a) + 1e-12f) : NEG_INF;
    }
    __syncthreads();

    // ---- pass 1 (DRAM): masked mean accumulation + stage first 64 tokens ----
    {
        float4 acc = make_float4(0.f, 0.f, 0.f, 0.f);
#pragma unroll
        for (int k = 0; k < (TT * DD / 4) / NTHREADS; ++k) {  // 25
            int i = tid + k * NTHREADS;
            float4 v = row4[i];
            if (k < (STG_T * DD / 4) / NTHREADS)   // k<8 -> t<64
                stg4[i] = v;
            float m = s_mask[i >> 5];
            acc.x += m * v.x; acc.y += m * v.y; acc.z += m * v.z; acc.w += m * v.w;
        }
        ((float4*)s_part)[tid] = acc;
        if (warp == 0) {
            float c = 0.f;
            for (int t = lane; t < TT; t += 32) c += s_mask[t];
            c = warp_sum(c);
            if (lane == 0) s_scal[0] = c;
        }
    }
    __syncthreads();
    const float cntf = s_scal[0];

    if (tid < DD) {
        int d4 = tid >> 2, comp = tid & 3;
        float s = 0.f;
#pragma unroll
        for (int j = 0; j < 8; ++j)
            s += s_part[(j * 32 + d4) * 4 + comp];
        s_mean[tid] = s / (cntf + 1e-6f);
    }
    __syncthreads();

    // ---- q[i] = dot(Wq row i, mean): warp-per-i, coalesced ----
    {
        float4 mv = ((const float4*)s_mean)[lane];
#pragma unroll
        for (int k = 0; k < 16; ++k) {
            int i = warp + k * 8;
            float4 w4 = ((const float4*)(Wq + (size_t)i * DD))[lane];
            float d = w4.x * mv.x + w4.y * mv.y + w4.z * mv.z + w4.w * mv.w;
            d = warp_sum(d);
            if (lane == 0) s_q[i] = d;
        }
    }
    __syncthreads();

    // ---- r[d] = sum_i q[i]*Wk[i,d], i split over halves, coalesced ----
    {
        int e = tid & 127, half = tid >> 7;
        const float* Kp = Wk + (size_t)half * 64 * DD + e;
        const float* qp = s_q + half * 64;
        float r = 0.f;
#pragma unroll 16
        for (int i = 0; i < 64; ++i)
            r += qp[i] * Kp[(size_t)i * DD];
        s_part[half * DD + e] = r;
    }
    __syncthreads();
    if (tid < DD) s_r[tid] = s_part[tid] + s_part[DD + tid];
    __syncthreads();

    // ---- pass 2: fused scores + online softmax + weighted sum ----
    const float scale = 0.08838834764831845f;  // 1/sqrt(128)
    {
        float4 rv = ((const float4*)s_r)[lane];
        float m = NEG_INF, Z = 0.f;
        float4 acc = make_float4(0.f, 0.f, 0.f, 0.f);
#pragma unroll
        for (int kb = 0; kb < 5; ++kb) {
            float4 xv[5];
            float  dt[5];
#pragma unroll
            for (int j = 0; j < 5; ++j) {
                int idx = kb * 5 + j;
                int t = warp + idx * 8;
                xv[j] = (idx < 8) ? stg4[t * 32 + lane] : row4[t * 32 + lane];
            }
#pragma unroll
            for (int j = 0; j < 5; ++j) {
                float d = xv[j].x * rv.x + xv[j].y * rv.y +
                          xv[j].z * rv.z + xv[j].w * rv.w;
                dt[j] = warp_sum(d);
            }
#pragma unroll
            for (int j = 0; j < 5; ++j) {
                int t = warp + (kb * 5 + j) * 8;
                float dl = s_dlog[t];
                if (dl != NEG_INF) {
                    float s = dt[j] * scale + dl;
                    if (s > m) {
                        float c = __expf(m - s);
                        Z *= c;
                        acc.x *= c; acc.y *= c; acc.z *= c; acc.w *= c;
                        m = s;
                    }
                    float p = __expf(s - m);
                    Z += p;
                    acc.x += p * xv[j].x; acc.y += p * xv[j].y;
                    acc.z += p * xv[j].z; acc.w += p * xv[j].w;
                }
            }
        }
        ((float4*)s_part)[warp * 32 + lane] = acc;
        if (lane == 0) { s_wm[warp] = m; s_wz[warp] = Z; }
    }
    __syncthreads();

    // ---- merge warp states, write normalized w to global scratch ----
    if (tid < DD) {
        float M = s_wm[0];
#pragma unroll
        for (int j = 1; j < 8; ++j) M = fmaxf(M, s_wm[j]);
        float Zt = 0.f, w = 0.f;
#pragma unroll
        for (int j = 0; j < 8; ++j) {
            float f = __expf(s_wm[j] - M);
            Zt += f * s_wz[j];
            w  += f * s_part[j * DD + tid];
        }
        g_w[(size_t)b * DD + tid] = w / Zt;
    }

    // ---- short-term window, gate; write pre-gated parts ----
    if (tid < DD) {
        int cnt = (int)(cntf + 0.5f);
        if (cnt < 1) cnt = 1;
        int start = cnt - KS;
        if (start < 0) start = 0;
        float dn = (float)(cnt - start);

        float st = 0.f;
        for (int t = start; t < cnt; ++t)
            st += (cnt <= STG_T) ? s_stage[t * DD + tid] : row[t * DD + tid];
        st /= dn;

        float mp = 0.f, mr = 0.f;
        for (int t = start; t < cnt; ++t) { mp += s_pop[t]; mr += s_age[t]; }
        mp /= dn; mr /= dn;

        float z = mp * gate_w[0] + mr * gate_w[1] + gate_b[0];
        float g = 1.f / (1.f + __expf(-z));
        g_us[(size_t)b * DD + tid] = g * st;
        if (tid == 0) g_omg[b] = 1.f - g;
    }
}

// combine v2: LT = w @ Wv^T with Wv staged in 2 chunks of 64 e-rows,
// float4 smem math, 256 blocks of 16 rows. Then gate-combine + LN.
__global__ void __launch_bounds__(NTHREADS, 4)
combine_kernel(const float* __restrict__ Wv,
               const float* __restrict__ ln_g,
               const float* __restrict__ ln_b,
               float* __restrict__ out) {
    extern __shared__ float cs[];
    float* wv_s = cs;                                // [ECHUNK][WV_P]
    float* w_s  = cs + ECHUNK * WV_P;                // [CB_ROWS][DD]
    float* lt_s = cs + ECHUNK * WV_P + CB_ROWS * DD; // [CB_ROWS][DD]
    float4* wv4 = (float4*)wv_s;
    float4* w4s = (float4*)w_s;

    const int tid  = threadIdx.x;
    const int lane = tid & 31;
    const int warp = tid >> 5;
    const int row0 = blockIdx.x * CB_ROWS;
    const int r0 = warp * 2;

    // load w rows (16x128 = 512 float4)
#pragma unroll
    for (int k = 0; k < 2; ++k)
        w4s[tid + k * NTHREADS] =
            ((const float4*)(g_w + (size_t)row0 * DD))[tid + k * NTHREADS];

    float a00 = 0.f, a01 = 0.f, a10 = 0.f, a11 = 0.f;

#pragma unroll
    for (int c = 0; c < 2; ++c) {
        __syncthreads();
        // stage Wv rows [c*64, c*64+64): 64 rows x 32 float4 = 2048 float4
#pragma unroll
        for (int k = 0; k < 8; ++k) {
            int i = tid + k * NTHREADS;
            int e_l = i >> 5, d4 = i & 31;
            wv4[e_l * 33 + d4] =
                ((const float4*)(Wv + (size_t)(c * ECHUNK + e_l) * DD))[d4];
        }
        __syncthreads();

        a00 = 0.f; a01 = 0.f; a10 = 0.f; a11 = 0.f;
#pragma unroll 8
        for (int d4 = 0; d4 < 32; ++d4) {
            float4 wr0 = w4s[r0 * 32 + d4];
            float4 wr1 = w4s[(r0 + 1) * 32 + d4];
            float4 v0  = wv4[lane * 33 + d4];
            float4 v1  = wv4[(lane + 32) * 33 + d4];
            a00 += wr0.x * v0.x + wr0.y * v0.y + wr0.z * v0.z + wr0.w * v0.w;
            a01 += wr0.x * v1.x + wr0.y * v1.y + wr0.z * v1.z + wr0.w * v1.w;
            a10 += wr1.x * v0.x + wr1.y * v0.y + wr1.z * v0.z + wr1.w * v0.w;
            a11 += wr1.x * v1.x + wr1.y * v1.y + wr1.z * v1.z + wr1.w * v1.w;
        }
        int e0 = c * ECHUNK + lane;
        lt_s[r0 * DD + e0]            = a00;
        lt_s[r0 * DD + e0 + 32]       = a01;
        lt_s[(r0 + 1) * DD + e0]      = a10;
        lt_s[(r0 + 1) * DD + e0 + 32] = a11;
    }
    __syncthreads();

    // LN: 2 rows per warp
    const float4 lg4 = ((const float4*)ln_g)[lane];
    const float4 lb4 = ((const float4*)ln_b)[lane];
#pragma unroll
    for (int i = 0; i < 2; ++i) {
        int rr = r0 + i;
        int grow = row0 + rr;
        float4 lt4 = ((const float4*)(lt_s + rr * DD))[lane];
        float4 us4 = ((const float4*)(g_us + (size_t)grow * DD))[lane];
        float om = g_omg[grow];
        float4 u;
        u.x = us4.x + om * lt4.x; u.y = us4.y + om * lt4.y;
        u.z = us4.z + om * lt4.z; u.w = us4.w + om * lt4.w;
        float mu = warp_sum(u.x + u.y + u.z + u.w) * (1.f / 128.f);
        float dx = u.x - mu, dy = u.y - mu, dz = u.z - mu, dw = u.w - mu;
        float var = warp_sum(dx * dx + dy * dy + dz * dz + dw * dw) * (1.f / 128.f);
        float rs = rsqrtf(var + 1e-5f);
        float4 o;
        o.x = dx * rs * lg4.x + lb4.x; o.y = dy * rs * lg4.y + lb4.y;
        o.z = dz * rs * lg4.z + lb4.z; o.w = dw * rs * lg4.w + lb4.w;
        ((float4*)(out + (size_t)grow * DD))[lane] = o;
    }
}

extern "C" void kernel_launch(void* const* d_in, const int* in_sizes, int n_in,
                              void* d_out, int out_size) {
    const float* items = (const float*)d_in[0];
    const int*   mask  = (const int*)d_in[1];
    const float* age   = (const float*)d_in[2];
    const float* pop   = (const float*)d_in[3];
    const float* Wq    = (const float*)d_in[4];
    const float* Wk    = (const float*)d_in[5];
    const float* Wv    = (const float*)d_in[6];
    const float* gw    = (const float*)d_in[7];
    const float* gb    = (const float*)d_in[8];
    const float* lng   = (const float*)d_in[9];
    const float* lnb   = (const float*)d_in[10];
    const float* da    = (const float*)d_in[11];
    float* out = (float*)d_out;

    user_enc_kernel<<<BB, NTHREADS>>>(items, mask, age, pop, Wq, Wk, gw, gb, da);
    cudaFuncSetAttribute(combine_kernel,
                         cudaFuncAttributeMaxDynamicSharedMemorySize, CB_SMEM);
    combine_kernel<<<BB / CB_ROWS, NTHREADS, CB_SMEM>>>(Wv, lng, lnb, out);
}

// round 9
// speedup vs baseline: 1.2222x; 1.2222x over previous
#include <cuda_runtime.h>

#define BB 4096
#define TT 200
#define DD 128
#define KS 5
#define NTHREADS 256

#define STG_T 64                 // tokens staged in smem for pass 2

#define CB_ROWS 32
#define WV_P4 33                 // float4s per padded Wv row (odd -> conflict-free)
#define CB_SMEM ((DD * WV_P4 * 4 + CB_ROWS * DD) * 4)

__device__ float g_w[BB * DD];    // normalized attention-weighted sum
__device__ float g_us[BB * DD];   // g * short_term
__device__ float g_omg[BB];       // 1 - g

__device__ __forceinline__ float warp_sum(float v) {
#pragma unroll
    for (int o = 16; o; o >>= 1) v += __shfl_xor_sync(0xffffffffu, v, o);
    return v;
}

__global__ void __launch_bounds__(NTHREADS, 4)
user_enc_kernel(const float* __restrict__ items_g,
                const int* __restrict__ mask_g,
                const float* __restrict__ age_g,
                const float* __restrict__ pop_g,
                const float* __restrict__ Wq,
                const float* __restrict__ Wk,
                const float* __restrict__ gate_w,
                const float* __restrict__ gate_b,
                const float* __restrict__ dalpha) {
    __shared__ float s_stage[STG_T * DD];   // 32 KB: first 64 tokens
    __shared__ float s_mask[TT];
    __shared__ float s_age[TT];
    __shared__ float s_pop[TT];
    __shared__ float s_dlog[TT];
    __shared__ float s_mean[DD];
    __shared__ float s_q[DD];
    __shared__ float s_r[DD];
    __shared__ float s_part[1024];
    __shared__ float s_wm[8];
    __shared__ float s_wz[8];
    __shared__ float s_scal[4];

    const int tid  = threadIdx.x;
    const int lane = tid & 31;
    const int warp = tid >> 5;
    const int b    = blockIdx.x;
    const float NEG_INF = __int_as_float(0xff800000);
    const float* row = items_g + (size_t)b * TT * DD;
    const float4* row4 = (const float4*)row;
    float4* stg4 = (float4*)s_stage;

    // ---- phase 0: metadata + decay-log (parallel) ----
    const float alpha = log1pf(expf(dalpha[0])) + 1e-6f;
    if (tid < TT) {
        int m = mask_g[(size_t)b * TT + tid];
        float a = age_g[(size_t)b * TT + tid];
        s_mask[tid] = m ? 1.f : 0.f;
        s_age[tid]  = a;
        s_pop[tid]  = pop_g[(size_t)b * TT + tid];
        s_dlog[tid] = m ? __logf(__expf(-alpha * a) + 1e-12f) : NEG_INF;
    }
    __syncthreads();

    // ---- pass 1 (DRAM): masked mean accumulation + stage first 64 tokens ----
    {
        float4 acc = make_float4(0.f, 0.f, 0.f, 0.f);
#pragma unroll
        for (int k = 0; k < (TT * DD / 4) / NTHREADS; ++k) {  // 25
            int i = tid + k * NTHREADS;
            float4 v = row4[i];
            if (k < (STG_T * DD / 4) / NTHREADS)   // k<8 -> t<64
                stg4[i] = v;
            float m = s_mask[i >> 5];
            acc.x += m * v.x; acc.y += m * v.y; acc.z += m * v.z; acc.w += m * v.w;
        }
        ((float4*)s_part)[tid] = acc;
        if (warp == 0) {
            float c = 0.f;
            for (int t = lane; t < TT; t += 32) c += s_mask[t];
            c = warp_sum(c);
            if (lane == 0) s_scal[0] = c;
        }
    }
    __syncthreads();
    const float cntf = s_scal[0];

    if (tid < DD) {
        int d4 = tid >> 2, comp = tid & 3;
        float s = 0.f;
#pragma unroll
        for (int j = 0; j < 8; ++j)
            s += s_part[(j * 32 + d4) * 4 + comp];
        s_mean[tid] = s / (cntf + 1e-6f);
    }
    __syncthreads();

    // ---- q[i] = dot(Wq row i, mean): warp-per-i, coalesced ----
    {
        float4 mv = ((const float4*)s_mean)[lane];
#pragma unroll
        for (int k = 0; k < 16; ++k) {
            int i = warp + k * 8;
            float4 w4 = ((const float4*)(Wq + (size_t)i * DD))[lane];
            float d = w4.x * mv.x + w4.y * mv.y + w4.z * mv.z + w4.w * mv.w;
            d = warp_sum(d);
            if (lane == 0) s_q[i] = d;
        }
    }
    __syncthreads();

    // ---- r[d] = sum_i q[i]*Wk[i,d], i split over halves, coalesced ----
    {
        int e = tid & 127, half = tid >> 7;
        const float* Kp = Wk + (size_t)half * 64 * DD + e;
        const float* qp = s_q + half * 64;
        float r = 0.f;
#pragma unroll 16
        for (int i = 0; i < 64; ++i)
            r += qp[i] * Kp[(size_t)i * DD];
        s_part[half * DD + e] = r;
    }
    __syncthreads();
    if (tid < DD) s_r[tid] = s_part[tid] + s_part[DD + tid];
    __syncthreads();

    // ---- pass 2: fused scores + online softmax + weighted sum ----
    const float scale = 0.08838834764831845f;  // 1/sqrt(128)
    {
        float4 rv = ((const float4*)s_r)[lane];
        float m = NEG_INF, Z = 0.f;
        float4 acc = make_float4(0.f, 0.f, 0.f, 0.f);
#pragma unroll
        for (int kb = 0; kb < 5; ++kb) {
            float4 xv[5];
            float  dt[5];
#pragma unroll
            for (int j = 0; j < 5; ++j) {
                int idx = kb * 5 + j;
                int t = warp + idx * 8;
                xv[j] = (idx < 8) ? stg4[t * 32 + lane] : row4[t * 32 + lane];
            }
#pragma unroll
            for (int j = 0; j < 5; ++j) {
                float d = xv[j].x * rv.x + xv[j].y * rv.y +
                          xv[j].z * rv.z + xv[j].w * rv.w;
                dt[j] = warp_sum(d);
            }
#pragma unroll
            for (int j = 0; j < 5; ++j) {
                int t = warp + (kb * 5 + j) * 8;
                float dl = s_dlog[t];
                if (dl != NEG_INF) {
                    float s = dt[j] * scale + dl;
                    if (s > m) {
                        float c = __expf(m - s);
                        Z *= c;
                        acc.x *= c; acc.y *= c; acc.z *= c; acc.w *= c;
                        m = s;
                    }
                    float p = __expf(s - m);
                    Z += p;
                    acc.x += p * xv[j].x; acc.y += p * xv[j].y;
                    acc.z += p * xv[j].z; acc.w += p * xv[j].w;
                }
            }
        }
        ((float4*)s_part)[warp * 32 + lane] = acc;
        if (lane == 0) { s_wm[warp] = m; s_wz[warp] = Z; }
    }
    __syncthreads();

    // ---- merge warp states, write normalized w to global scratch ----
    if (tid < DD) {
        float M = s_wm[0];
#pragma unroll
        for (int j = 1; j < 8; ++j) M = fmaxf(M, s_wm[j]);
        float Zt = 0.f, w = 0.f;
#pragma unroll
        for (int j = 0; j < 8; ++j) {
            float f = __expf(s_wm[j] - M);
            Zt += f * s_wz[j];
            w  += f * s_part[j * DD + tid];
        }
        g_w[(size_t)b * DD + tid] = w / Zt;
    }

    // ---- short-term window, gate; write pre-gated parts ----
    if (tid < DD) {
        int cnt = (int)(cntf + 0.5f);
        if (cnt < 1) cnt = 1;
        int start = cnt - KS;
        if (start < 0) start = 0;
        float dn = (float)(cnt - start);

        float st = 0.f;
        for (int t = start; t < cnt; ++t)
            st += (cnt <= STG_T) ? s_stage[t * DD + tid] : row[t * DD + tid];
        st /= dn;

        float mp = 0.f, mr = 0.f;
        for (int t = start; t < cnt; ++t) { mp += s_pop[t]; mr += s_age[t]; }
        mp /= dn; mr /= dn;

        float z = mp * gate_w[0] + mr * gate_w[1] + gate_b[0];
        float g = 1.f / (1.f + __expf(-z));
        g_us[(size_t)b * DD + tid] = g * st;
        if (tid == 0) g_omg[b] = 1.f - g;
    }
}

// combine: LT = w @ Wv^T, full Wv staged once (float4-padded), float4 LDS GEMM,
// then user = g_us + (1-g)*LT, LayerNorm, out. Grid 128 x 32 rows.
__global__ void __launch_bounds__(NTHREADS, 1)
combine_kernel(const float* __restrict__ Wv,
               const float* __restrict__ ln_g,
               const float* __restrict__ ln_b,
               float* __restrict__ out) {
    extern __shared__ float cs[];
    float4* wv4 = (float4*)cs;                     // [DD][WV_P4] float4s
    float*  w_s = cs + DD * WV_P4 * 4;             // [CB_ROWS][DD], reused for LT
    float4* w4s = (float4*)w_s;

    const int tid  = threadIdx.x;
    const int lane = tid & 31;
    const int warp = tid >> 5;
    const int row0 = blockIdx.x * CB_ROWS;
    const int r0 = warp * 4;

    // stage Wv: 4096 float4 -> padded rows (stride 33 float4, conflict-free)
#pragma unroll
    for (int k = 0; k < 16; ++k) {
        int i = tid + k * NTHREADS;
        int e = i >> 5, d4 = i & 31;
        wv4[e * WV_P4 + d4] = ((const float4*)Wv)[i];
    }
    // load w rows (32x128 = 1024 float4)
#pragma unroll
    for (int k = 0; k < 4; ++k) {
        int i = tid + k * NTHREADS;
        w4s[i] = ((const float4*)(g_w + (size_t)row0 * DD))[i];
    }
    __syncthreads();

    // GEMM: thread tile 4 rows x 4 e, float4 over d (32 iters)
    float acc[4][4] = {};
#pragma unroll 4
    for (int d4 = 0; d4 < 32; ++d4) {
        float4 wr[4], vv[4];
#pragma unroll
        for (int i = 0; i < 4; ++i) wr[i] = w4s[(r0 + i) * 32 + d4];
#pragma unroll
        for (int j = 0; j < 4; ++j) vv[j] = wv4[(lane + 32 * j) * WV_P4 + d4];
#pragma unroll
        for (int i = 0; i < 4; ++i)
#pragma unroll
            for (int j = 0; j < 4; ++j)
                acc[i][j] += wr[i].x * vv[j].x + wr[i].y * vv[j].y +
                             wr[i].z * vv[j].z + wr[i].w * vv[j].w;
    }
    __syncthreads();
    // store LT into w_s (w fully consumed)
#pragma unroll
    for (int i = 0; i < 4; ++i)
#pragma unroll
        for (int j = 0; j < 4; ++j)
            w_s[(r0 + i) * DD + lane + 32 * j] = acc[i][j];
    __syncthreads();

    // LN: warp per row (4 rows per warp)
    const float4 lg4 = ((const float4*)ln_g)[lane];
    const float4 lb4 = ((const float4*)ln_b)[lane];
#pragma unroll
    for (int i = 0; i < 4; ++i) {
        int rr = warp * 4 + i;
        int grow = row0 + rr;
        float4 lt4 = ((const float4*)(w_s + rr * DD))[lane];
        float4 us4 = ((const float4*)(g_us + (size_t)grow * DD))[lane];
        float om = g_omg[grow];
        float4 u;
        u.x = us4.x + om * lt4.x; u.y = us4.y + om * lt4.y;
        u.z = us4.z + om * lt4.z; u.w = us4.w + om * lt4.w;
        float mu = warp_sum(u.x + u.y + u.z + u.w) * (1.f / 128.f);
        float dx = u.x - mu, dy = u.y - mu, dz = u.z - mu, dw = u.w - mu;
        float var = warp_sum(dx * dx + dy * dy + dz * dz + dw * dw) * (1.f / 128.f);
        float rs = rsqrtf(var + 1e-5f);
        float4 o;
        o.x = dx * rs * lg4.x + lb4.x; o.y = dy * rs * lg4.y + lb4.y;
        o.z = dz * rs * lg4.z + lb4.z; o.w = dw * rs * lg4.w + lb4.w;
        ((float4*)(out + (size_t)grow * DD))[lane] = o;
    }
}

extern "C" void kernel_launch(void* const* d_in, const int* in_sizes, int n_in,
                              void* d_out, int out_size) {
    const float* items = (const float*)d_in[0];
    const int*   mask  = (const int*)d_in[1];
    const float* age   = (const float*)d_in[2];
    const float* pop   = (const float*)d_in[3];
    const float* Wq    = (const float*)d_in[4];
    const float* Wk    = (const float*)d_in[5];
    const float* Wv    = (const float*)d_in[6];
    const float* gw    = (const float*)d_in[7];
    const float* gb    = (const float*)d_in[8];
    const float* lng   = (const float*)d_in[9];
    const float* lnb   = (const float*)d_in[10];
    const float* da    = (const float*)d_in[11];
    float* out = (float*)d_out;

    user_enc_kernel<<<BB, NTHREADS>>>(items, mask, age, pop, Wq, Wk, gw, gb, da);
    cudaFuncSetAttribute(combine_kernel,
                         cudaFuncAttributeMaxDynamicSharedMemorySize, CB_SMEM);
    combine_kernel<<<BB / CB_ROWS, NTHREADS, CB_SMEM>>>(Wv, lng, lnb, out);
}